// round 6
// baseline (speedup 1.0000x reference)
#include <cuda_runtime.h>
#include <cstdint>

#define Nn 32000
#define Ee 512000
#define Fk 256
#define Hh 4
#define Dd 64
#define Cc 256          // Hh * Dd
#define NEG 0.2f

// ---------------- scratch (device globals: no allocation allowed) ----------
__device__ float g_ft[Nn * Cc];        // projected features [N, 256]
__device__ float g_esrc[Nn * Hh];      // per-node src logits
__device__ float g_edst[Nn * Hh];      // per-node dst logits
__device__ int   g_count[Nn];          // in-degree
__device__ int   g_off[Nn];            // CSR offsets (exclusive scan of count)
__device__ int   g_cur[Nn];            // scatter cursors
__device__ int   g_elist[Ee];          // edge ids grouped by dst

// ---------------- tf32 tensor-core GEMM: ft = feat @ W ---------------------
// [32000,256] x [256,256], BM=128 BN=64 BK=32, 8 warps, warp tile 32x32.
// BN == head width, so per-head attention logits are computed in the epilogue
// from the register accumulators (no ft re-read, no extra kernel).
#define BM 128
#define BN 64
#define BK 32
#define PA 36   // A smem pitch (floats) -> conflict-free fragment reads
#define PB 72   // B smem pitch (floats) -> conflict-free fragment reads

__device__ __forceinline__ uint32_t f2tf(float f) {
    uint32_t o;
    asm("cvt.rna.tf32.f32 %0, %1;" : "=r"(o) : "f"(f));
    return o;
}

__device__ __forceinline__ void mma_tf32(float c[4],
                                         const uint32_t a[4],
                                         const uint32_t b[2]) {
    asm volatile(
        "mma.sync.aligned.m16n8k8.row.col.f32.tf32.tf32.f32 "
        "{%0,%1,%2,%3}, {%4,%5,%6,%7}, {%8,%9}, {%0,%1,%2,%3};"
        : "+f"(c[0]), "+f"(c[1]), "+f"(c[2]), "+f"(c[3])
        : "r"(a[0]), "r"(a[1]), "r"(a[2]), "r"(a[3]),
          "r"(b[0]), "r"(b[1]));
}

__global__ void gemm_tc_kernel(const float* __restrict__ A,
                               const float* __restrict__ B,
                               const float* __restrict__ wsrc,
                               const float* __restrict__ wdst) {
    __shared__ uint32_t As[BM * PA];   // 18432 B
    __shared__ uint32_t Bs[BK * PB];   //  9216 B
    __shared__ float s_ps[BM][2];      // att partials per row, per wn-half
    __shared__ float s_pd[BM][2];

    const int tid  = threadIdx.x;
    const int lane = tid & 31;
    const int warp = tid >> 5;
    const int wm   = warp >> 1;        // 0..3 (M)
    const int wn   = warp & 1;         // 0..1 (N)
    const int row0 = blockIdx.x * BM;
    const int col0 = blockIdx.y * BN;
    const int hd   = blockIdx.y;       // head index (BN == head width)

    float c[2][4][4];
    #pragma unroll
    for (int mt = 0; mt < 2; mt++)
        #pragma unroll
        for (int nt = 0; nt < 4; nt++)
            #pragma unroll
            for (int r = 0; r < 4; r++) c[mt][nt][r] = 0.f;

    // staging coordinates
    const int ar = tid >> 3;           // A: row within 32-row pass
    const int ac = (tid & 7) * 4;      // A: col (float4)
    const int br = tid >> 4;           // B: row within 16-row pass
    const int bc = (tid & 15) * 4;     // B: col (float4)

    float4 pa[4], pb[2];
    #pragma unroll
    for (int p = 0; p < 4; p++)
        pa[p] = *reinterpret_cast<const float4*>(
            &A[(row0 + ar + p * 32) * Fk + ac]);
    #pragma unroll
    for (int p = 0; p < 2; p++)
        pb[p] = *reinterpret_cast<const float4*>(
            &B[(br + p * 16) * Cc + col0 + bc]);

    const int NTILES = Fk / BK;        // 8
    for (int t = 0; t < NTILES; t++) {
        // store staged regs to smem with tf32 round-to-nearest
        #pragma unroll
        for (int p = 0; p < 4; p++) {
            uint32_t* d = &As[(ar + p * 32) * PA + ac];
            d[0] = f2tf(pa[p].x); d[1] = f2tf(pa[p].y);
            d[2] = f2tf(pa[p].z); d[3] = f2tf(pa[p].w);
        }
        #pragma unroll
        for (int p = 0; p < 2; p++) {
            uint32_t* d = &Bs[(br + p * 16) * PB + bc];
            d[0] = f2tf(pb[p].x); d[1] = f2tf(pb[p].y);
            d[2] = f2tf(pb[p].z); d[3] = f2tf(pb[p].w);
        }
        __syncthreads();

        // prefetch next tile
        if (t + 1 < NTILES) {
            int k0 = (t + 1) * BK;
            #pragma unroll
            for (int p = 0; p < 4; p++)
                pa[p] = *reinterpret_cast<const float4*>(
                    &A[(row0 + ar + p * 32) * Fk + k0 + ac]);
            #pragma unroll
            for (int p = 0; p < 2; p++)
                pb[p] = *reinterpret_cast<const float4*>(
                    &B[(k0 + br + p * 16) * Cc + col0 + bc]);
        }

        // 4 k-steps of 8
        #pragma unroll
        for (int ks = 0; ks < 4; ks++) {
            const int kk = ks * 8;
            uint32_t af[2][4], bf[4][2];
            #pragma unroll
            for (int mt = 0; mt < 2; mt++) {
                int r = wm * 32 + mt * 16 + (lane >> 2);
                af[mt][0] = As[r * PA + kk + (lane & 3)];
                af[mt][1] = As[(r + 8) * PA + kk + (lane & 3)];
                af[mt][2] = As[r * PA + kk + (lane & 3) + 4];
                af[mt][3] = As[(r + 8) * PA + kk + (lane & 3) + 4];
            }
            #pragma unroll
            for (int nt = 0; nt < 4; nt++) {
                int nc = wn * 32 + nt * 8 + (lane >> 2);
                bf[nt][0] = Bs[(kk + (lane & 3)) * PB + nc];
                bf[nt][1] = Bs[(kk + (lane & 3) + 4) * PB + nc];
            }
            #pragma unroll
            for (int mt = 0; mt < 2; mt++)
                #pragma unroll
                for (int nt = 0; nt < 4; nt++)
                    mma_tf32(c[mt][nt], af[mt], bf[nt]);
        }
        __syncthreads();
    }

    // epilogue 1: write ft accumulators
    #pragma unroll
    for (int mt = 0; mt < 2; mt++) {
        #pragma unroll
        for (int nt = 0; nt < 4; nt++) {
            int r  = row0 + wm * 32 + mt * 16 + (lane >> 2);
            int cc = col0 + wn * 32 + nt * 8 + 2 * (lane & 3);
            *reinterpret_cast<float2*>(&g_ft[r * Cc + cc]) =
                make_float2(c[mt][nt][0], c[mt][nt][1]);
            *reinterpret_cast<float2*>(&g_ft[(r + 8) * Cc + cc]) =
                make_float2(c[mt][nt][2], c[mt][nt][3]);
        }
    }

    // epilogue 2: attention logits for head hd from register accumulators.
    float2 ws2[4], wd2[4];
    #pragma unroll
    for (int nt = 0; nt < 4; nt++) {
        int cl = wn * 32 + nt * 8 + 2 * (lane & 3);
        ws2[nt] = *reinterpret_cast<const float2*>(&wsrc[hd * Dd + cl]);
        wd2[nt] = *reinterpret_cast<const float2*>(&wdst[hd * Dd + cl]);
    }
    #pragma unroll
    for (int mt = 0; mt < 2; mt++) {
        float ps0 = 0.f, pd0 = 0.f, ps1 = 0.f, pd1 = 0.f;
        #pragma unroll
        for (int nt = 0; nt < 4; nt++) {
            ps0 += c[mt][nt][0] * ws2[nt].x + c[mt][nt][1] * ws2[nt].y;
            pd0 += c[mt][nt][0] * wd2[nt].x + c[mt][nt][1] * wd2[nt].y;
            ps1 += c[mt][nt][2] * ws2[nt].x + c[mt][nt][3] * ws2[nt].y;
            pd1 += c[mt][nt][2] * wd2[nt].x + c[mt][nt][3] * wd2[nt].y;
        }
        // reduce over the quad (lanes differing in bits 0..1 share the row)
        #pragma unroll
        for (int m = 1; m < 4; m <<= 1) {
            ps0 += __shfl_xor_sync(0xffffffffu, ps0, m);
            pd0 += __shfl_xor_sync(0xffffffffu, pd0, m);
            ps1 += __shfl_xor_sync(0xffffffffu, ps1, m);
            pd1 += __shfl_xor_sync(0xffffffffu, pd1, m);
        }
        if ((lane & 3) == 0) {
            int r = wm * 32 + mt * 16 + (lane >> 2);
            s_ps[r][wn]     = ps0;  s_pd[r][wn]     = pd0;
            s_ps[r + 8][wn] = ps1;  s_pd[r + 8][wn] = pd1;
        }
    }
    __syncthreads();
    if (tid < BM) {
        g_esrc[(row0 + tid) * Hh + hd] = s_ps[tid][0] + s_ps[tid][1];
        g_edst[(row0 + tid) * Hh + hd] = s_pd[tid][0] + s_pd[tid][1];
    }
}

// ---------------- CSR build -------------------------------------------------
__global__ void zero_kernel() {
    int i = blockIdx.x * blockDim.x + threadIdx.x;
    if (i < Nn) g_count[i] = 0;
}

__global__ void hist_kernel(const int* __restrict__ dst) {
    int e = blockIdx.x * blockDim.x + threadIdx.x;
    if (e < Ee) atomicAdd(&g_count[dst[e]], 1);
}

__global__ void scan_kernel() {
    __shared__ int warpsums[32];
    int tid  = threadIdx.x;
    int lane = tid & 31;
    int wid  = tid >> 5;
    int carry = 0;

    for (int base = 0; base < Nn; base += 1024) {
        int i = base + tid;
        int v = (i < Nn) ? g_count[i] : 0;
        int x = v;
        #pragma unroll
        for (int d = 1; d < 32; d <<= 1) {
            int y = __shfl_up_sync(0xffffffffu, x, d);
            if (lane >= d) x += y;
        }
        if (lane == 31) warpsums[wid] = x;
        __syncthreads();
        if (wid == 0) {
            int s = warpsums[lane];
            #pragma unroll
            for (int d = 1; d < 32; d <<= 1) {
                int y = __shfl_up_sync(0xffffffffu, s, d);
                if (lane >= d) s += y;
            }
            warpsums[lane] = s;
        }
        __syncthreads();
        int add  = (wid > 0) ? warpsums[wid - 1] : 0;
        int excl = x - v + add + carry;
        if (i < Nn) { g_off[i] = excl; g_cur[i] = excl; }
        carry += warpsums[31];
        __syncthreads();
    }
}

__global__ void scatter_kernel(const int* __restrict__ dst) {
    int e = blockIdx.x * blockDim.x + threadIdx.x;
    if (e < Ee) {
        int d = dst[e];
        int p = atomicAdd(&g_cur[d], 1);
        g_elist[p] = e;
    }
}

// ---------------- softmax + aggregation ------------------------------------
// online-softmax pair combine: (m, s) <- (m, s) ⊕ (m2, s2)
__device__ __forceinline__ void msum(float& m, float& s, float m2, float s2) {
    float mn = fmaxf(m, m2);
    float a = (s  != 0.f) ? s  * __expf(m  - mn) : 0.f;
    float b = (s2 != 0.f) ? s2 * __expf(m2 - mn) : 0.f;
    m = mn; s = a + b;
}

#define ETILE 64

// one block per destination node, 256 threads = one output element each.
__global__ void agg_kernel(const float* __restrict__ dist,
                           const int* __restrict__ src,
                           float* __restrict__ out) {
    const int n    = blockIdx.x;
    const int tid  = threadIdx.x;
    const int lane = tid & 31;
    const int wrp  = tid >> 5;
    const int off  = g_off[n];
    const int deg  = g_count[n];

    __shared__ float s_max[Hh];
    __shared__ float s_rden[Hh];
    __shared__ float s_edst[Hh];
    __shared__ float s_wm[8][Hh];     // per-warp online (m, s)
    __shared__ float s_ws[8][Hh];
    __shared__ int   s_src[ETILE];
    __shared__ float s_a[ETILE][Hh];

    if (tid < Hh) s_edst[tid] = g_edst[n * Hh + tid];
    __syncthreads();

    const float NEGINF = __int_as_float(0xff800000);

    // single online-softmax pass: per-thread (m, s), warp reduce, block combine
    {
        float lm[Hh] = {NEGINF, NEGINF, NEGINF, NEGINF};
        float ls[Hh] = {0.f, 0.f, 0.f, 0.f};
        for (int i = tid; i < deg; i += 256) {
            int e = g_elist[off + i];
            int s = src[e];
            float4 es = *reinterpret_cast<const float4*>(&g_esrc[s * Hh]);
            float ev[Hh] = {es.x, es.y, es.z, es.w};
            #pragma unroll
            for (int h = 0; h < Hh; h++) {
                float v = ev[h] + s_edst[h];
                v = (v >= 0.f) ? v : NEG * v;
                float mn = fmaxf(lm[h], v);
                float a  = (ls[h] != 0.f) ? ls[h] * __expf(lm[h] - mn) : 0.f;
                ls[h] = a + __expf(v - mn);
                lm[h] = mn;
            }
        }
        // warp shuffle-tree reduce of (m, s) pairs
        #pragma unroll
        for (int d = 16; d > 0; d >>= 1) {
            #pragma unroll
            for (int h = 0; h < Hh; h++) {
                float m2 = __shfl_xor_sync(0xffffffffu, lm[h], d);
                float s2 = __shfl_xor_sync(0xffffffffu, ls[h], d);
                msum(lm[h], ls[h], m2, s2);
            }
        }
        if (lane == 0) {
            #pragma unroll
            for (int h = 0; h < Hh; h++) { s_wm[wrp][h] = lm[h]; s_ws[wrp][h] = ls[h]; }
        }
    }
    __syncthreads();
    // combine the 8 per-warp pairs: warp 0, thread = h*8 + w
    if (wrp == 0) {
        int h = lane >> 3;     // 0..3
        int w = lane & 7;      // 0..7
        float m = s_wm[w][h];
        float s = s_ws[w][h];
        #pragma unroll
        for (int d = 1; d < 8; d <<= 1) {
            float m2 = __shfl_xor_sync(0xffffffffu, m, d);
            float s2 = __shfl_xor_sync(0xffffffffu, s, d);
            msum(m, s, m2, s2);
        }
        if (w == 0) {
            s_max[h]  = m;
            s_rden[h] = (s > 0.f) ? 1.f / s : 0.f;
        }
    }
    __syncthreads();

    // phase C: tiled weighted aggregation (scalars via smem, ft coalesced)
    const int h = tid >> 6;
    float acc = 0.f;

    for (int t0 = 0; t0 < deg; t0 += ETILE) {
        const int tl = min(ETILE, deg - t0);
        {
            int i  = tid >> 2;
            int hh = tid & 3;
            if (i < tl) {
                int e = g_elist[off + t0 + i];
                int s = src[e];
                if (hh == 0) s_src[i] = s;
                float v = g_esrc[s * Hh + hh] + s_edst[hh];
                v = (v >= 0.f) ? v : NEG * v;
                s_a[i][hh] = __expf(v - s_max[hh]) * s_rden[hh] * dist[e];
            }
        }
        __syncthreads();

        for (int i = 0; i < tl; i++) {
            acc += g_ft[s_src[i] * Cc + tid] * s_a[i][h];
        }
        __syncthreads();
    }

    out[n * Cc + tid] = acc;
}

// ---------------- launch ----------------------------------------------------
extern "C" void kernel_launch(void* const* d_in, const int* in_sizes, int n_in,
                              void* d_out, int out_size) {
    const float* feat = (const float*)d_in[0];
    const float* dist = (const float*)d_in[1];
    const float* W    = (const float*)d_in[2];
    const float* wsrc = (const float*)d_in[3];
    const float* wdst = (const float*)d_in[4];
    const int*   src  = (const int*)d_in[5];
    const int*   dst  = (const int*)d_in[6];
    float*       out  = (float*)d_out;

    (void)in_sizes; (void)n_in; (void)out_size;

    gemm_tc_kernel<<<dim3(Nn / BM, Cc / BN), 256>>>(feat, W, wsrc, wdst);
    zero_kernel<<<(Nn + 255) / 256, 256>>>();
    hist_kernel<<<(Ee + 255) / 256, 256>>>(dst);
    scan_kernel<<<1, 1024>>>();
    scatter_kernel<<<(Ee + 255) / 256, 256>>>(dst);
    agg_kernel<<<Nn, 256>>>(dist, src, out);
}

// round 7
// speedup vs baseline: 1.0362x; 1.0362x over previous
#include <cuda_runtime.h>
#include <cstdint>

#define Nn 32000
#define Ee 512000
#define Fk 256
#define Hh 4
#define Dd 64
#define Cc 256          // Hh * Dd
#define NEG 0.2f

// ---------------- scratch (device globals: no allocation allowed) ----------
__device__ float g_ft[Nn * Cc];        // projected features [N, 256]
__device__ float g_esrc[Nn * Hh];      // per-node src logits
__device__ float g_edst[Nn * Hh];      // per-node dst logits
__device__ int   g_count[Nn];          // in-degree
__device__ int   g_off[Nn];            // CSR offsets (exclusive scan of count)
__device__ int   g_cur[Nn];            // scatter cursors
__device__ int   g_bsum[125];          // per-block count sums (32000/256)
__device__ int   g_boff[125];          // scanned block offsets
__device__ int   g_srclist[Ee];        // src node per CSR slot
__device__ float g_dlist[Ee];          // dist per CSR slot
__device__ float g_vlist[Ee * Hh];     // esrc[src] per CSR slot (4 floats)

// ---------------- tf32 tensor-core GEMM: ft = feat @ W ---------------------
// [32000,256] x [256,256], BM=128 BN=64 BK=32, 8 warps, warp tile 32x32.
// BN == head width: per-head attention logits computed in the epilogue.
#define BM 128
#define BN 64
#define BK 32
#define PA 36   // A smem pitch (floats) -> conflict-free fragment reads
#define PB 72   // B smem pitch (floats) -> conflict-free fragment reads

__device__ __forceinline__ uint32_t f2tf(float f) {
    uint32_t o;
    asm("cvt.rna.tf32.f32 %0, %1;" : "=r"(o) : "f"(f));
    return o;
}

__device__ __forceinline__ void mma_tf32(float c[4],
                                         const uint32_t a[4],
                                         const uint32_t b[2]) {
    asm volatile(
        "mma.sync.aligned.m16n8k8.row.col.f32.tf32.tf32.f32 "
        "{%0,%1,%2,%3}, {%4,%5,%6,%7}, {%8,%9}, {%0,%1,%2,%3};"
        : "+f"(c[0]), "+f"(c[1]), "+f"(c[2]), "+f"(c[3])
        : "r"(a[0]), "r"(a[1]), "r"(a[2]), "r"(a[3]),
          "r"(b[0]), "r"(b[1]));
}

__global__ void gemm_tc_kernel(const float* __restrict__ A,
                               const float* __restrict__ B,
                               const float* __restrict__ wsrc,
                               const float* __restrict__ wdst) {
    __shared__ uint32_t As[BM * PA];
    __shared__ uint32_t Bs[BK * PB];
    __shared__ float s_ps[BM][2];
    __shared__ float s_pd[BM][2];

    const int tid  = threadIdx.x;
    const int lane = tid & 31;
    const int warp = tid >> 5;
    const int wm   = warp >> 1;
    const int wn   = warp & 1;
    const int row0 = blockIdx.x * BM;
    const int col0 = blockIdx.y * BN;
    const int hd   = blockIdx.y;

    float c[2][4][4];
    #pragma unroll
    for (int mt = 0; mt < 2; mt++)
        #pragma unroll
        for (int nt = 0; nt < 4; nt++)
            #pragma unroll
            for (int r = 0; r < 4; r++) c[mt][nt][r] = 0.f;

    const int ar = tid >> 3;
    const int ac = (tid & 7) * 4;
    const int br = tid >> 4;
    const int bc = (tid & 15) * 4;

    float4 pa[4], pb[2];
    #pragma unroll
    for (int p = 0; p < 4; p++)
        pa[p] = *reinterpret_cast<const float4*>(
            &A[(row0 + ar + p * 32) * Fk + ac]);
    #pragma unroll
    for (int p = 0; p < 2; p++)
        pb[p] = *reinterpret_cast<const float4*>(
            &B[(br + p * 16) * Cc + col0 + bc]);

    const int NTILES = Fk / BK;
    for (int t = 0; t < NTILES; t++) {
        #pragma unroll
        for (int p = 0; p < 4; p++) {
            uint32_t* d = &As[(ar + p * 32) * PA + ac];
            d[0] = f2tf(pa[p].x); d[1] = f2tf(pa[p].y);
            d[2] = f2tf(pa[p].z); d[3] = f2tf(pa[p].w);
        }
        #pragma unroll
        for (int p = 0; p < 2; p++) {
            uint32_t* d = &Bs[(br + p * 16) * PB + bc];
            d[0] = f2tf(pb[p].x); d[1] = f2tf(pb[p].y);
            d[2] = f2tf(pb[p].z); d[3] = f2tf(pb[p].w);
        }
        __syncthreads();

        if (t + 1 < NTILES) {
            int k0 = (t + 1) * BK;
            #pragma unroll
            for (int p = 0; p < 4; p++)
                pa[p] = *reinterpret_cast<const float4*>(
                    &A[(row0 + ar + p * 32) * Fk + k0 + ac]);
            #pragma unroll
            for (int p = 0; p < 2; p++)
                pb[p] = *reinterpret_cast<const float4*>(
                    &B[(k0 + br + p * 16) * Cc + col0 + bc]);
        }

        #pragma unroll
        for (int ks = 0; ks < 4; ks++) {
            const int kk = ks * 8;
            uint32_t af[2][4], bf[4][2];
            #pragma unroll
            for (int mt = 0; mt < 2; mt++) {
                int r = wm * 32 + mt * 16 + (lane >> 2);
                af[mt][0] = As[r * PA + kk + (lane & 3)];
                af[mt][1] = As[(r + 8) * PA + kk + (lane & 3)];
                af[mt][2] = As[r * PA + kk + (lane & 3) + 4];
                af[mt][3] = As[(r + 8) * PA + kk + (lane & 3) + 4];
            }
            #pragma unroll
            for (int nt = 0; nt < 4; nt++) {
                int nc = wn * 32 + nt * 8 + (lane >> 2);
                bf[nt][0] = Bs[(kk + (lane & 3)) * PB + nc];
                bf[nt][1] = Bs[(kk + (lane & 3) + 4) * PB + nc];
            }
            #pragma unroll
            for (int mt = 0; mt < 2; mt++)
                #pragma unroll
                for (int nt = 0; nt < 4; nt++)
                    mma_tf32(c[mt][nt], af[mt], bf[nt]);
        }
        __syncthreads();
    }

    // epilogue 1: write ft accumulators
    #pragma unroll
    for (int mt = 0; mt < 2; mt++) {
        #pragma unroll
        for (int nt = 0; nt < 4; nt++) {
            int r  = row0 + wm * 32 + mt * 16 + (lane >> 2);
            int cc = col0 + wn * 32 + nt * 8 + 2 * (lane & 3);
            *reinterpret_cast<float2*>(&g_ft[r * Cc + cc]) =
                make_float2(c[mt][nt][0], c[mt][nt][1]);
            *reinterpret_cast<float2*>(&g_ft[(r + 8) * Cc + cc]) =
                make_float2(c[mt][nt][2], c[mt][nt][3]);
        }
    }

    // epilogue 2: attention logits for head hd from register accumulators
    float2 ws2[4], wd2[4];
    #pragma unroll
    for (int nt = 0; nt < 4; nt++) {
        int cl = wn * 32 + nt * 8 + 2 * (lane & 3);
        ws2[nt] = *reinterpret_cast<const float2*>(&wsrc[hd * Dd + cl]);
        wd2[nt] = *reinterpret_cast<const float2*>(&wdst[hd * Dd + cl]);
    }
    #pragma unroll
    for (int mt = 0; mt < 2; mt++) {
        float ps0 = 0.f, pd0 = 0.f, ps1 = 0.f, pd1 = 0.f;
        #pragma unroll
        for (int nt = 0; nt < 4; nt++) {
            ps0 += c[mt][nt][0] * ws2[nt].x + c[mt][nt][1] * ws2[nt].y;
            pd0 += c[mt][nt][0] * wd2[nt].x + c[mt][nt][1] * wd2[nt].y;
            ps1 += c[mt][nt][2] * ws2[nt].x + c[mt][nt][3] * ws2[nt].y;
            pd1 += c[mt][nt][2] * wd2[nt].x + c[mt][nt][3] * wd2[nt].y;
        }
        #pragma unroll
        for (int m = 1; m < 4; m <<= 1) {
            ps0 += __shfl_xor_sync(0xffffffffu, ps0, m);
            pd0 += __shfl_xor_sync(0xffffffffu, pd0, m);
            ps1 += __shfl_xor_sync(0xffffffffu, ps1, m);
            pd1 += __shfl_xor_sync(0xffffffffu, pd1, m);
        }
        if ((lane & 3) == 0) {
            int r = wm * 32 + mt * 16 + (lane >> 2);
            s_ps[r][wn]     = ps0;  s_pd[r][wn]     = pd0;
            s_ps[r + 8][wn] = ps1;  s_pd[r + 8][wn] = pd1;
        }
    }
    __syncthreads();
    if (tid < BM) {
        g_esrc[(row0 + tid) * Hh + hd] = s_ps[tid][0] + s_ps[tid][1];
        g_edst[(row0 + tid) * Hh + hd] = s_pd[tid][0] + s_pd[tid][1];
    }
}

// ---------------- CSR build -------------------------------------------------
__global__ void zero_kernel() {
    int i = blockIdx.x * blockDim.x + threadIdx.x;
    if (i < Nn) g_count[i] = 0;
}

__global__ void hist_kernel(const int* __restrict__ dst) {
    int e = blockIdx.x * blockDim.x + threadIdx.x;
    if (e < Ee) atomicAdd(&g_count[dst[e]], 1);
}

// scan stage 1: per-block sums (125 blocks x 256, 125*256 == 32000)
__global__ void bsum_kernel() {
    __shared__ int ws[8];
    int t = threadIdx.x, lane = t & 31, w = t >> 5;
    int v = g_count[blockIdx.x * 256 + t];
    #pragma unroll
    for (int d = 16; d > 0; d >>= 1) v += __shfl_xor_sync(0xffffffffu, v, d);
    if (lane == 0) ws[w] = v;
    __syncthreads();
    if (t == 0) {
        int s = 0;
        #pragma unroll
        for (int k = 0; k < 8; k++) s += ws[k];
        g_bsum[blockIdx.x] = s;
    }
}

// scan stage 2: exclusive scan of the 125 block sums (1 block, 128 threads)
__global__ void bscan_kernel() {
    __shared__ int ws[4];
    int t = threadIdx.x, lane = t & 31, w = t >> 5;
    int v = (t < 125) ? g_bsum[t] : 0;
    int x = v;
    #pragma unroll
    for (int d = 1; d < 32; d <<= 1) {
        int y = __shfl_up_sync(0xffffffffu, x, d);
        if (lane >= d) x += y;
    }
    if (lane == 31) ws[w] = x;
    __syncthreads();
    if (t == 0) {
        int a = 0;
        #pragma unroll
        for (int k = 0; k < 4; k++) { int tmp = ws[k]; ws[k] = a; a += tmp; }
    }
    __syncthreads();
    if (t < 125) g_boff[t] = x - v + ws[w];
}

// scan stage 3: local exclusive scan + block offset (125 blocks x 256)
__global__ void addscan_kernel() {
    __shared__ int ws[8];
    __shared__ int wo[8];
    int b = blockIdx.x, t = threadIdx.x, lane = t & 31, w = t >> 5;
    int i = b * 256 + t;
    int v = g_count[i];
    int x = v;
    #pragma unroll
    for (int d = 1; d < 32; d <<= 1) {
        int y = __shfl_up_sync(0xffffffffu, x, d);
        if (lane >= d) x += y;
    }
    if (lane == 31) ws[w] = x;
    __syncthreads();
    if (t == 0) {
        int a = 0;
        #pragma unroll
        for (int k = 0; k < 8; k++) { wo[k] = a; a += ws[k]; }
    }
    __syncthreads();
    int excl = x - v + wo[w] + g_boff[b];
    g_off[i] = excl;
    g_cur[i] = excl;
}

// scatter: assign CSR slots AND pre-gather per-edge data so agg streams
// everything coalesced (src id, dist, esrc[src] 4 floats per slot).
__global__ void scatter_kernel(const int* __restrict__ src,
                               const int* __restrict__ dst,
                               const float* __restrict__ dist) {
    int e = blockIdx.x * blockDim.x + threadIdx.x;
    if (e < Ee) {
        int d = dst[e];
        int s = src[e];
        int p = atomicAdd(&g_cur[d], 1);
        g_srclist[p] = s;
        g_dlist[p]   = dist[e];
        float4 es = *reinterpret_cast<const float4*>(&g_esrc[s * Hh]);
        *reinterpret_cast<float4*>(&g_vlist[p * Hh]) = es;
    }
}

// ---------------- softmax + aggregation ------------------------------------
__device__ __forceinline__ void msum(float& m, float& s, float m2, float s2) {
    float mn = fmaxf(m, m2);
    float a = (s  != 0.f) ? s  * __expf(m  - mn) : 0.f;
    float b = (s2 != 0.f) ? s2 * __expf(m2 - mn) : 0.f;
    m = mn; s = a + b;
}

#define ETILE 64

// one block per destination node, 256 threads = one output element each.
__global__ void agg_kernel(float* __restrict__ out) {
    const int n    = blockIdx.x;
    const int tid  = threadIdx.x;
    const int lane = tid & 31;
    const int wrp  = tid >> 5;
    const int off  = g_off[n];
    const int deg  = g_count[n];

    __shared__ float s_max[Hh];
    __shared__ float s_rden[Hh];
    __shared__ float s_edst[Hh];
    __shared__ float s_wm[8][Hh];
    __shared__ float s_ws[8][Hh];
    __shared__ int   s_src[ETILE];
    __shared__ float s_a[ETILE][Hh];

    if (tid < Hh) s_edst[tid] = g_edst[n * Hh + tid];
    __syncthreads();

    const float NEGINF = __int_as_float(0xff800000);

    // single online-softmax pass — fully coalesced vlist reads
    {
        float lm[Hh] = {NEGINF, NEGINF, NEGINF, NEGINF};
        float ls[Hh] = {0.f, 0.f, 0.f, 0.f};
        for (int i = tid; i < deg; i += 256) {
            float4 es = *reinterpret_cast<const float4*>(&g_vlist[(off + i) * Hh]);
            float ev[Hh] = {es.x, es.y, es.z, es.w};
            #pragma unroll
            for (int h = 0; h < Hh; h++) {
                float v = ev[h] + s_edst[h];
                v = (v >= 0.f) ? v : NEG * v;
                float mn = fmaxf(lm[h], v);
                float a  = (ls[h] != 0.f) ? ls[h] * __expf(lm[h] - mn) : 0.f;
                ls[h] = a + __expf(v - mn);
                lm[h] = mn;
            }
        }
        #pragma unroll
        for (int d = 16; d > 0; d >>= 1) {
            #pragma unroll
            for (int h = 0; h < Hh; h++) {
                float m2 = __shfl_xor_sync(0xffffffffu, lm[h], d);
                float s2 = __shfl_xor_sync(0xffffffffu, ls[h], d);
                msum(lm[h], ls[h], m2, s2);
            }
        }
        if (lane == 0) {
            #pragma unroll
            for (int h = 0; h < Hh; h++) { s_wm[wrp][h] = lm[h]; s_ws[wrp][h] = ls[h]; }
        }
    }
    __syncthreads();
    if (wrp == 0) {
        int h = lane >> 3;
        int w = lane & 7;
        float m = s_wm[w][h];
        float s = s_ws[w][h];
        #pragma unroll
        for (int d = 1; d < 8; d <<= 1) {
            float m2 = __shfl_xor_sync(0xffffffffu, m, d);
            float s2 = __shfl_xor_sync(0xffffffffu, s, d);
            msum(m, s, m2, s2);
        }
        if (w == 0) {
            s_max[h]  = m;
            s_rden[h] = (s > 0.f) ? 1.f / s : 0.f;
        }
    }
    __syncthreads();

    // phase C: tiled weighted aggregation; coefficients coalesced from vlist
    const int h = tid >> 6;
    float acc = 0.f;

    for (int t0 = 0; t0 < deg; t0 += ETILE) {
        const int tl = min(ETILE, deg - t0);
        {
            int i  = tid >> 2;
            int hh = tid & 3;
            if (i < tl) {
                int p = off + t0 + i;
                if (hh == 0) s_src[i] = g_srclist[p];
                // linear index: p*Hh + hh == (off+t0)*Hh + tid  -> coalesced
                float v = g_vlist[p * Hh + hh] + s_edst[hh];
                v = (v >= 0.f) ? v : NEG * v;
                s_a[i][hh] = __expf(v - s_max[hh]) * s_rden[hh] * g_dlist[p];
            }
        }
        __syncthreads();

        int i = 0;
        for (; i + 4 <= tl; i += 4) {
            int   s0 = s_src[i],     s1 = s_src[i + 1];
            int   s2 = s_src[i + 2], s3 = s_src[i + 3];
            float f0 = g_ft[s0 * Cc + tid];
            float f1 = g_ft[s1 * Cc + tid];
            float f2 = g_ft[s2 * Cc + tid];
            float f3 = g_ft[s3 * Cc + tid];
            acc += f0 * s_a[i][h]     + f1 * s_a[i + 1][h]
                 + f2 * s_a[i + 2][h] + f3 * s_a[i + 3][h];
        }
        for (; i < tl; i++) {
            acc += g_ft[s_src[i] * Cc + tid] * s_a[i][h];
        }
        __syncthreads();
    }

    out[n * Cc + tid] = acc;
}

// ---------------- launch ----------------------------------------------------
extern "C" void kernel_launch(void* const* d_in, const int* in_sizes, int n_in,
                              void* d_out, int out_size) {
    const float* feat = (const float*)d_in[0];
    const float* dist = (const float*)d_in[1];
    const float* W    = (const float*)d_in[2];
    const float* wsrc = (const float*)d_in[3];
    const float* wdst = (const float*)d_in[4];
    const int*   src  = (const int*)d_in[5];
    const int*   dst  = (const int*)d_in[6];
    float*       out  = (float*)d_out;

    (void)in_sizes; (void)n_in; (void)out_size;

    gemm_tc_kernel<<<dim3(Nn / BM, Cc / BN), 256>>>(feat, W, wsrc, wdst);
    zero_kernel<<<(Nn + 255) / 256, 256>>>();
    hist_kernel<<<(Ee + 255) / 256, 256>>>(dst);
    bsum_kernel<<<125, 256>>>();
    bscan_kernel<<<1, 128>>>();
    addscan_kernel<<<125, 256>>>();
    scatter_kernel<<<(Ee + 255) / 256, 256>>>(src, dst, dist);
    agg_kernel<<<Nn, 256>>>(out);
}

// round 9
// speedup vs baseline: 1.0389x; 1.0026x over previous
#include <cuda_runtime.h>
#include <cstdint>

#define Nn 32000
#define Ee 512000
#define Fk 256
#define Hh 4
#define Dd 64
#define Cc 256          // Hh * Dd
#define NEG 0.2f

// ---------------- scratch (device globals: no allocation allowed) ----------
__device__ float g_ft[Nn * Cc];        // projected features [N, 256]
__device__ float g_esrc[Nn * Hh];      // per-node src logits
__device__ float g_edst[Nn * Hh];      // per-node dst logits
__device__ int   g_count[Nn];          // in-degree (zeroed by agg for next replay)
__device__ int   g_off[Nn];            // CSR offsets
__device__ int   g_cur[Nn];            // scatter cursors
__device__ int   g_srclist[Ee];        // src node per CSR slot
__device__ float g_dlist[Ee];          // dist per CSR slot
__device__ float g_vlist[Ee * Hh];     // esrc[src] per CSR slot (4 floats)

// ---------------- tf32 tensor-core GEMM: ft = feat @ W ---------------------
#define BM 128
#define BN 64
#define BK 32
#define PA 36   // A smem pitch (floats) -> conflict-free fragment reads
#define PB 72   // B smem pitch (floats) -> conflict-free fragment reads

__device__ __forceinline__ uint32_t f2tf(float f) {
    uint32_t o;
    asm("cvt.rna.tf32.f32 %0, %1;" : "=r"(o) : "f"(f));
    return o;
}

__device__ __forceinline__ void mma_tf32(float c[4],
                                         const uint32_t a[4],
                                         const uint32_t b[2]) {
    asm volatile(
        "mma.sync.aligned.m16n8k8.row.col.f32.tf32.tf32.f32 "
        "{%0,%1,%2,%3}, {%4,%5,%6,%7}, {%8,%9}, {%0,%1,%2,%3};"
        : "+f"(c[0]), "+f"(c[1]), "+f"(c[2]), "+f"(c[3])
        : "r"(a[0]), "r"(a[1]), "r"(a[2]), "r"(a[3]),
          "r"(b[0]), "r"(b[1]));
}

__global__ void gemm_tc_kernel(const float* __restrict__ A,
                               const float* __restrict__ B,
                               const float* __restrict__ wsrc,
                               const float* __restrict__ wdst) {
    __shared__ uint32_t As[BM * PA];
    __shared__ uint32_t Bs[BK * PB];
    __shared__ float s_ps[BM][2];
    __shared__ float s_pd[BM][2];

    const int tid  = threadIdx.x;
    const int lane = tid & 31;
    const int warp = tid >> 5;
    const int wm   = warp >> 1;
    const int wn   = warp & 1;
    const int row0 = blockIdx.x * BM;
    const int col0 = blockIdx.y * BN;
    const int hd   = blockIdx.y;

    float c[2][4][4];
    #pragma unroll
    for (int mt = 0; mt < 2; mt++)
        #pragma unroll
        for (int nt = 0; nt < 4; nt++)
            #pragma unroll
            for (int r = 0; r < 4; r++) c[mt][nt][r] = 0.f;

    const int ar = tid >> 3;
    const int ac = (tid & 7) * 4;
    const int br = tid >> 4;
    const int bc = (tid & 15) * 4;

    float4 pa[4], pb[2];
    #pragma unroll
    for (int p = 0; p < 4; p++)
        pa[p] = *reinterpret_cast<const float4*>(
            &A[(row0 + ar + p * 32) * Fk + ac]);
    #pragma unroll
    for (int p = 0; p < 2; p++)
        pb[p] = *reinterpret_cast<const float4*>(
            &B[(br + p * 16) * Cc + col0 + bc]);

    const int NTILES = Fk / BK;
    for (int t = 0; t < NTILES; t++) {
        #pragma unroll
        for (int p = 0; p < 4; p++) {
            uint32_t* d = &As[(ar + p * 32) * PA + ac];
            d[0] = f2tf(pa[p].x); d[1] = f2tf(pa[p].y);
            d[2] = f2tf(pa[p].z); d[3] = f2tf(pa[p].w);
        }
        #pragma unroll
        for (int p = 0; p < 2; p++) {
            uint32_t* d = &Bs[(br + p * 16) * PB + bc];
            d[0] = f2tf(pb[p].x); d[1] = f2tf(pb[p].y);
            d[2] = f2tf(pb[p].z); d[3] = f2tf(pb[p].w);
        }
        __syncthreads();

        if (t + 1 < NTILES) {
            int k0 = (t + 1) * BK;
            #pragma unroll
            for (int p = 0; p < 4; p++)
                pa[p] = *reinterpret_cast<const float4*>(
                    &A[(row0 + ar + p * 32) * Fk + k0 + ac]);
            #pragma unroll
            for (int p = 0; p < 2; p++)
                pb[p] = *reinterpret_cast<const float4*>(
                    &B[(k0 + br + p * 16) * Cc + col0 + bc]);
        }

        #pragma unroll
        for (int ks = 0; ks < 4; ks++) {
            const int kk = ks * 8;
            uint32_t af[2][4], bf[4][2];
            #pragma unroll
            for (int mt = 0; mt < 2; mt++) {
                int r = wm * 32 + mt * 16 + (lane >> 2);
                af[mt][0] = As[r * PA + kk + (lane & 3)];
                af[mt][1] = As[(r + 8) * PA + kk + (lane & 3)];
                af[mt][2] = As[r * PA + kk + (lane & 3) + 4];
                af[mt][3] = As[(r + 8) * PA + kk + (lane & 3) + 4];
            }
            #pragma unroll
            for (int nt = 0; nt < 4; nt++) {
                int nc = wn * 32 + nt * 8 + (lane >> 2);
                bf[nt][0] = Bs[(kk + (lane & 3)) * PB + nc];
                bf[nt][1] = Bs[(kk + (lane & 3) + 4) * PB + nc];
            }
            #pragma unroll
            for (int mt = 0; mt < 2; mt++)
                #pragma unroll
                for (int nt = 0; nt < 4; nt++)
                    mma_tf32(c[mt][nt], af[mt], bf[nt]);
        }
        __syncthreads();
    }

    // epilogue 1: write ft accumulators
    #pragma unroll
    for (int mt = 0; mt < 2; mt++) {
        #pragma unroll
        for (int nt = 0; nt < 4; nt++) {
            int r  = row0 + wm * 32 + mt * 16 + (lane >> 2);
            int cc = col0 + wn * 32 + nt * 8 + 2 * (lane & 3);
            *reinterpret_cast<float2*>(&g_ft[r * Cc + cc]) =
                make_float2(c[mt][nt][0], c[mt][nt][1]);
            *reinterpret_cast<float2*>(&g_ft[(r + 8) * Cc + cc]) =
                make_float2(c[mt][nt][2], c[mt][nt][3]);
        }
    }

    // epilogue 2: attention logits for head hd from register accumulators
    float2 ws2[4], wd2[4];
    #pragma unroll
    for (int nt = 0; nt < 4; nt++) {
        int cl = wn * 32 + nt * 8 + 2 * (lane & 3);
        ws2[nt] = *reinterpret_cast<const float2*>(&wsrc[hd * Dd + cl]);
        wd2[nt] = *reinterpret_cast<const float2*>(&wdst[hd * Dd + cl]);
    }
    #pragma unroll
    for (int mt = 0; mt < 2; mt++) {
        float ps0 = 0.f, pd0 = 0.f, ps1 = 0.f, pd1 = 0.f;
        #pragma unroll
        for (int nt = 0; nt < 4; nt++) {
            ps0 += c[mt][nt][0] * ws2[nt].x + c[mt][nt][1] * ws2[nt].y;
            pd0 += c[mt][nt][0] * wd2[nt].x + c[mt][nt][1] * wd2[nt].y;
            ps1 += c[mt][nt][2] * ws2[nt].x + c[mt][nt][3] * ws2[nt].y;
            pd1 += c[mt][nt][2] * wd2[nt].x + c[mt][nt][3] * wd2[nt].y;
        }
        #pragma unroll
        for (int m = 1; m < 4; m <<= 1) {
            ps0 += __shfl_xor_sync(0xffffffffu, ps0, m);
            pd0 += __shfl_xor_sync(0xffffffffu, pd0, m);
            ps1 += __shfl_xor_sync(0xffffffffu, ps1, m);
            pd1 += __shfl_xor_sync(0xffffffffu, pd1, m);
        }
        if ((lane & 3) == 0) {
            int r = wm * 32 + mt * 16 + (lane >> 2);
            s_ps[r][wn]     = ps0;  s_pd[r][wn]     = pd0;
            s_ps[r + 8][wn] = ps1;  s_pd[r + 8][wn] = pd1;
        }
    }
    __syncthreads();
    if (tid < BM) {
        g_esrc[(row0 + tid) * Hh + hd] = s_ps[tid][0] + s_ps[tid][1];
        g_edst[(row0 + tid) * Hh + hd] = s_pd[tid][0] + s_pd[tid][1];
    }
}

// ---------------- CSR build -------------------------------------------------
__global__ void hist_kernel(const int* __restrict__ dst) {
    int e = blockIdx.x * blockDim.x + threadIdx.x;
    if (e < Ee) atomicAdd(&g_count[dst[e]], 1);
}

// fused scan (125 blocks x 256, 125*256 == 32000): block b computes its
// global offset by reducing g_count[0 .. b*256) (L2-resident, coalesced),
// then local exclusive scan of its own 256 counts.
__global__ void scan_kernel() {
    __shared__ int ws[8];
    __shared__ int wo[8];
    __shared__ int s_boff;
    int b = blockIdx.x, t = threadIdx.x, lane = t & 31, w = t >> 5;

    // global offset: sum of all counts before this block's segment
    {
        int p = 0;
        for (int i = t; i < b * 256; i += 256) p += g_count[i];
        #pragma unroll
        for (int d = 16; d > 0; d >>= 1) p += __shfl_xor_sync(0xffffffffu, p, d);
        if (lane == 0) ws[w] = p;
        __syncthreads();
        if (t == 0) {
            int s = 0;
            #pragma unroll
            for (int k = 0; k < 8; k++) s += ws[k];
            s_boff = s;
        }
        __syncthreads();
    }

    int i = b * 256 + t;
    int v = g_count[i];
    int x = v;
    #pragma unroll
    for (int d = 1; d < 32; d <<= 1) {
        int y = __shfl_up_sync(0xffffffffu, x, d);
        if (lane >= d) x += y;
    }
    if (lane == 31) ws[w] = x;
    __syncthreads();
    if (t == 0) {
        int a = 0;
        #pragma unroll
        for (int k = 0; k < 8; k++) { wo[k] = a; a += ws[k]; }
    }
    __syncthreads();
    int excl = x - v + wo[w] + s_boff;
    g_off[i] = excl;
    g_cur[i] = excl;
}

// scatter: assign CSR slots, pre-gather per-edge data (runs after gemm so
// esrc is available).
__global__ void scatter_kernel(const int* __restrict__ src,
                               const int* __restrict__ dst,
                               const float* __restrict__ dist) {
    int e = blockIdx.x * blockDim.x + threadIdx.x;
    if (e < Ee) {
        int d = dst[e];
        int s = src[e];
        int p = atomicAdd(&g_cur[d], 1);
        g_srclist[p] = s;
        g_dlist[p]   = dist[e];
        float4 es = *reinterpret_cast<const float4*>(&g_esrc[s * Hh]);
        *reinterpret_cast<float4*>(&g_vlist[p * Hh]) = es;
    }
}

// ---------------- softmax + aggregation ------------------------------------
__device__ __forceinline__ void msum(float& m, float& s, float m2, float s2) {
    float mn = fmaxf(m, m2);
    float a = (s  != 0.f) ? s  * __expf(m  - mn) : 0.f;
    float b = (s2 != 0.f) ? s2 * __expf(m2 - mn) : 0.f;
    m = mn; s = a + b;
}

#define ETILE 64

// one block per destination node, 256 threads = one output element each.
// also zeroes g_count[n] for the next graph replay.
__global__ void agg_kernel(float* __restrict__ out) {
    const int n    = blockIdx.x;
    const int tid  = threadIdx.x;
    const int lane = tid & 31;
    const int wrp  = tid >> 5;
    const int off  = g_off[n];
    const int deg  = g_count[n];

    __shared__ float s_max[Hh];
    __shared__ float s_rden[Hh];
    __shared__ float s_edst[Hh];
    __shared__ float s_wm[8][Hh];
    __shared__ float s_ws[8][Hh];
    __shared__ int   s_src[ETILE];
    __shared__ float s_a[ETILE][Hh];

    if (tid < Hh) s_edst[tid] = g_edst[n * Hh + tid];
    __syncthreads();

    const float NEGINF = __int_as_float(0xff800000);

    // single online-softmax pass — fully coalesced vlist reads
    {
        float lm[Hh] = {NEGINF, NEGINF, NEGINF, NEGINF};
        float ls[Hh] = {0.f, 0.f, 0.f, 0.f};
        for (int i = tid; i < deg; i += 256) {
            float4 es = *reinterpret_cast<const float4*>(&g_vlist[(off + i) * Hh]);
            float ev[Hh] = {es.x, es.y, es.z, es.w};
            #pragma unroll
            for (int h = 0; h < Hh; h++) {
                float v = ev[h] + s_edst[h];
                v = (v >= 0.f) ? v : NEG * v;
                float mn = fmaxf(lm[h], v);
                float a  = (ls[h] != 0.f) ? ls[h] * __expf(lm[h] - mn) : 0.f;
                ls[h] = a + __expf(v - mn);
                lm[h] = mn;
            }
        }
        #pragma unroll
        for (int d = 16; d > 0; d >>= 1) {
            #pragma unroll
            for (int h = 0; h < Hh; h++) {
                float m2 = __shfl_xor_sync(0xffffffffu, lm[h], d);
                float s2 = __shfl_xor_sync(0xffffffffu, ls[h], d);
                msum(lm[h], ls[h], m2, s2);
            }
        }
        if (lane == 0) {
            #pragma unroll
            for (int h = 0; h < Hh; h++) { s_wm[wrp][h] = lm[h]; s_ws[wrp][h] = ls[h]; }
        }
    }
    __syncthreads();
    if (wrp == 0) {
        int h = lane >> 3;
        int w = lane & 7;
        float m = s_wm[w][h];
        float s = s_ws[w][h];
        #pragma unroll
        for (int d = 1; d < 8; d <<= 1) {
            float m2 = __shfl_xor_sync(0xffffffffu, m, d);
            float s2 = __shfl_xor_sync(0xffffffffu, s, d);
            msum(m, s, m2, s2);
        }
        if (w == 0) {
            s_max[h]  = m;
            s_rden[h] = (s > 0.f) ? 1.f / s : 0.f;
        }
    }
    __syncthreads();

    // phase C: tiled weighted aggregation; coefficients coalesced from vlist
    const int h = tid >> 6;
    float acc = 0.f;

    for (int t0 = 0; t0 < deg; t0 += ETILE) {
        const int tl = min(ETILE, deg - t0);
        {
            int i  = tid >> 2;
            int hh = tid & 3;
            if (i < tl) {
                int p = off + t0 + i;
                if (hh == 0) s_src[i] = g_srclist[p];
                float v = g_vlist[p * Hh + hh] + s_edst[hh];
                v = (v >= 0.f) ? v : NEG * v;
                s_a[i][hh] = __expf(v - s_max[hh]) * s_rden[hh] * g_dlist[p];
            }
        }
        __syncthreads();

        int i = 0;
        for (; i + 4 <= tl; i += 4) {
            int   s0 = s_src[i],     s1 = s_src[i + 1];
            int   s2 = s_src[i + 2], s3 = s_src[i + 3];
            float f0 = g_ft[s0 * Cc + tid];
            float f1 = g_ft[s1 * Cc + tid];
            float f2 = g_ft[s2 * Cc + tid];
            float f3 = g_ft[s3 * Cc + tid];
            acc += f0 * s_a[i][h]     + f1 * s_a[i + 1][h]
                 + f2 * s_a[i + 2][h] + f3 * s_a[i + 3][h];
        }
        for (; i < tl; i++) {
            acc += g_ft[s_src[i] * Cc + tid] * s_a[i][h];
        }
        __syncthreads();
    }

    out[n * Cc + tid] = acc;

    // reset in-degree for next graph replay (hist accumulates)
    if (tid == 0) g_count[n] = 0;
}

// ---------------- launch ----------------------------------------------------
extern "C" void kernel_launch(void* const* d_in, const int* in_sizes, int n_in,
                              void* d_out, int out_size) {
    const float* feat = (const float*)d_in[0];
    const float* dist = (const float*)d_in[1];
    const float* W    = (const float*)d_in[2];
    const float* wsrc = (const float*)d_in[3];
    const float* wdst = (const float*)d_in[4];
    const int*   src  = (const int*)d_in[5];
    const int*   dst  = (const int*)d_in[6];
    float*       out  = (float*)d_out;

    (void)in_sizes; (void)n_in; (void)out_size;

    gemm_tc_kernel<<<dim3(Nn / BM, Cc / BN), 256>>>(feat, W, wsrc, wdst);  // 0
    hist_kernel<<<(Ee + 255) / 256, 256>>>(dst);                            // 1
    scan_kernel<<<125, 256>>>();                                            // 2
    scatter_kernel<<<(Ee + 255) / 256, 256>>>(src, dst, dist);              // 3
    agg_kernel<<<Nn, 256>>>(out);                                           // 4
    // 5 launches/replay -> ncu (-s 5 -c 1) profiles replay-2's gemm
}